// round 1
// baseline (speedup 1.0000x reference)
#include <cuda_runtime.h>

// Problem constants
#define BROWS 4096
#define DIN   512
#define DH    256
#define DG    128
#define NHEAD 8
#define NCAT  3328   // 256 (h-branch) + 2048 (z1) + 1024 (z2)

// Scratch for the GEMM result: [B, NCAT] with layout per row:
//   [0,256)     raw x@Wh  (bias/relu/LN applied in phase 2)
//   [256,2304)  z1 = x@Wz1
//   [2304,3328) z2 = x@Wz2
__device__ float g_scratch[(size_t)BROWS * NCAT];

// ---------------------------------------------------------------------------
// Phase 1: C[4096,3328] = X[4096,512] @ [Wh | Wz1 | Wz2]
// Classic SGEMM: 128x128 block tile, k-tile 16, 256 threads, 8x8 per thread.
// ---------------------------------------------------------------------------
__global__ __launch_bounds__(256, 2)
void gemm_cat_kernel(const float* __restrict__ X,
                     const float* __restrict__ Wh,
                     const float* __restrict__ Wz1,
                     const float* __restrict__ Wz2)
{
    __shared__ float As[16][132];   // [k][m], padded
    __shared__ float Bs[16][128];   // [k][n]

    const int n0 = blockIdx.x * 128;
    const int m0 = blockIdx.y * 128;

    // Select which weight matrix this N-tile falls into (tiles never straddle:
    // segment widths 256 / 2048 / 1024 are all multiples of 128).
    const float* W;
    int ldN, wn0;
    if (n0 < 256)       { W = Wh;  ldN = 256;  wn0 = n0; }
    else if (n0 < 2304) { W = Wz1; ldN = 2048; wn0 = n0 - 256; }
    else                { W = Wz2; ldN = 1024; wn0 = n0 - 2304; }

    const int tid = threadIdx.x;
    const int tx  = tid & 15;      // n direction
    const int ty  = tid >> 4;      // m direction

    float acc[8][8];
    #pragma unroll
    for (int i = 0; i < 8; i++)
        #pragma unroll
        for (int j = 0; j < 8; j++) acc[i][j] = 0.f;

    for (int k0 = 0; k0 < DIN; k0 += 16) {
        // Load A tile: 128 rows x 16 k  = 512 float4, 2 per thread (transposed store)
        #pragma unroll
        for (int r = 0; r < 2; r++) {
            int f  = tid + r * 256;
            int m  = f >> 2;
            int k4 = (f & 3) * 4;
            float4 v = *(const float4*)(X + (size_t)(m0 + m) * DIN + k0 + k4);
            As[k4 + 0][m] = v.x;
            As[k4 + 1][m] = v.y;
            As[k4 + 2][m] = v.z;
            As[k4 + 3][m] = v.w;
        }
        // Load B tile: 16 k-rows x 128 n = 512 float4, 2 per thread
        #pragma unroll
        for (int r = 0; r < 2; r++) {
            int f  = tid + r * 256;
            int kr = f >> 5;
            int c4 = (f & 31) * 4;
            float4 v = *(const float4*)(W + (size_t)(k0 + kr) * ldN + wn0 + c4);
            *(float4*)(&Bs[kr][c4]) = v;
        }
        __syncthreads();

        #pragma unroll
        for (int kk = 0; kk < 16; kk++) {
            float a[8], b[8];
            *(float4*)(a)     = *(const float4*)(&As[kk][ty * 8]);
            *(float4*)(a + 4) = *(const float4*)(&As[kk][ty * 8 + 4]);
            *(float4*)(b)     = *(const float4*)(&Bs[kk][tx * 8]);
            *(float4*)(b + 4) = *(const float4*)(&Bs[kk][tx * 8 + 4]);
            #pragma unroll
            for (int i = 0; i < 8; i++)
                #pragma unroll
                for (int j = 0; j < 8; j++)
                    acc[i][j] = fmaf(a[i], b[j], acc[i][j]);
        }
        __syncthreads();
    }

    // Store to scratch
    #pragma unroll
    for (int i = 0; i < 8; i++) {
        int row = m0 + ty * 8 + i;
        float* dst = g_scratch + (size_t)row * NCAT + n0 + tx * 8;
        *(float4*)(dst)     = make_float4(acc[i][0], acc[i][1], acc[i][2], acc[i][3]);
        *(float4*)(dst + 4) = make_float4(acc[i][4], acc[i][5], acc[i][6], acc[i][7]);
    }
}

// ---------------------------------------------------------------------------
// Phase 2: per-row fusion. One block (256 threads = 8 warps) per batch row.
//   h   = LN(relu(a + bh)) * scale + bias           (a = scratch[:,0:256])
//   w[g,:] = sum_h z2[h,g] * z1[h,:]  (K=8, in registers, never to memory)
//   y[g] = sum_d tanh((w[g,d]-mu_g)/(sd_g+eps)) * h[d]
// Output layout assumed: out[0 .. B*256) = h flat, out[B*256 ..) = y flat.
// ---------------------------------------------------------------------------
__global__ __launch_bounds__(256, 4)
void fuse_kernel(const float* __restrict__ bh,
                 const float* __restrict__ ln_scale,
                 const float* __restrict__ ln_bias,
                 float* __restrict__ out)
{
    const int b   = blockIdx.x;
    const int tid = threadIdx.x;
    const int lane = tid & 31;
    const int wid  = tid >> 5;

    __shared__ float z1s[NHEAD * DH];   // 2048
    __shared__ float z2s[NHEAD * DG];   // 1024
    __shared__ float hs[DH];            // 256
    __shared__ float red[2][8];

    const float* base = g_scratch + (size_t)b * NCAT;

    // --- load z1, z2 into shared (vectorized) ---
    #pragma unroll
    for (int r = 0; r < 2; r++) {
        int f = tid + r * 256;
        ((float4*)z1s)[f] = ((const float4*)(base + 256))[f];
    }
    ((float4*)z2s)[tid] = ((const float4*)(base + 2304))[tid];

    // --- relu + bias + LayerNorm on the 256-wide branch (thread tid <-> d=tid) ---
    float v = fmaxf(base[tid] + bh[tid], 0.f);
    float s = v, q = v * v;
    #pragma unroll
    for (int o = 16; o; o >>= 1) {
        s += __shfl_xor_sync(0xffffffffu, s, o);
        q += __shfl_xor_sync(0xffffffffu, q, o);
    }
    if (lane == 0) { red[0][wid] = s; red[1][wid] = q; }
    __syncthreads();
    float ts = 0.f, tq = 0.f;
    #pragma unroll
    for (int i = 0; i < 8; i++) { ts += red[0][i]; tq += red[1][i]; }
    const float mu_ln  = ts * (1.f / 256.f);
    const float var_ln = tq * (1.f / 256.f) - mu_ln * mu_ln;
    const float inv_ln = rsqrtf(var_ln + 1e-6f);
    const float hv = (v - mu_ln) * inv_ln * ln_scale[tid] + ln_bias[tid];
    hs[tid] = hv;
    out[(size_t)b * DH + tid] = hv;          // h output
    __syncthreads();

    // --- per-g: build w row in registers, standardize, tanh, dot with h ---
    float* out_y = out + (size_t)BROWS * DH;
    #pragma unroll 1
    for (int gi = 0; gi < 16; gi++) {
        const int g = wid + gi * 8;          // each warp: 16 g values

        float zc[NHEAD];
        #pragma unroll
        for (int h = 0; h < NHEAD; h++) zc[h] = z2s[h * DG + g];   // broadcast

        float wv[8];
        float sw = 0.f, qw = 0.f;
        #pragma unroll
        for (int j = 0; j < 8; j++) {
            const int d = j * 32 + lane;
            float a = 0.f;
            #pragma unroll
            for (int h = 0; h < NHEAD; h++)
                a = fmaf(zc[h], z1s[h * DH + d], a);
            wv[j] = a;
            sw += a;
            qw = fmaf(a, a, qw);
        }
        #pragma unroll
        for (int o = 16; o; o >>= 1) {
            sw += __shfl_xor_sync(0xffffffffu, sw, o);
            qw += __shfl_xor_sync(0xffffffffu, qw, o);
        }
        const float mu  = sw * (1.f / 256.f);
        const float var = fmaxf(qw * (1.f / 256.f) - mu * mu, 0.f);
        const float sd  = sqrtf(var);
        const float inv = 1.f / (sd + 1e-6f);

        float y = 0.f;
        #pragma unroll
        for (int j = 0; j < 8; j++)
            y = fmaf(tanhf((wv[j] - mu) * inv), hs[j * 32 + lane], y);
        #pragma unroll
        for (int o = 16; o; o >>= 1)
            y += __shfl_xor_sync(0xffffffffu, y, o);
        if (lane == 0) out_y[(size_t)b * DG + g] = y;
    }
}

// ---------------------------------------------------------------------------
extern "C" void kernel_launch(void* const* d_in, const int* in_sizes, int n_in,
                              void* d_out, int out_size)
{
    const float* x        = (const float*)d_in[0];
    const float* Wh       = (const float*)d_in[1];
    const float* bh       = (const float*)d_in[2];
    const float* Wz1      = (const float*)d_in[3];
    const float* Wz2      = (const float*)d_in[4];
    const float* ln_scale = (const float*)d_in[5];
    const float* ln_bias  = (const float*)d_in[6];
    float* out = (float*)d_out;

    dim3 g1(NCAT / 128, BROWS / 128);   // 26 x 32
    gemm_cat_kernel<<<g1, 256>>>(x, Wh, Wz1, Wz2);
    fuse_kernel<<<BROWS, 256>>>(bh, ln_scale, ln_bias, out);
}

// round 2
// speedup vs baseline: 1.1333x; 1.1333x over previous
#include <cuda_runtime.h>

#define BROWS 4096
#define DIN   512
#define DH    256
#define DG    128
#define NHEAD 8
#define NCAT  3328   // 256 (h-branch) + 2048 (z1) + 1024 (z2)

__device__ float g_scratch[(size_t)BROWS * NCAT];

__device__ __forceinline__ float tanh_fast(float x) {
    float r;
    asm("tanh.approx.f32 %0, %1;" : "=f"(r) : "f"(x));
    return r;
}

// ---------------------------------------------------------------------------
// Phase 1: C[4096,3328] = X[4096,512] @ [Wh | Wz1 | Wz2]
// 128x128 tile, k-tile 16, 256 threads, 8x8/thread, double-buffered smem.
// ---------------------------------------------------------------------------
__global__ __launch_bounds__(256, 2)
void gemm_cat_kernel(const float* __restrict__ X,
                     const float* __restrict__ Wh,
                     const float* __restrict__ Wz1,
                     const float* __restrict__ Wz2)
{
    __shared__ float As[2][16][132];   // [buf][k][m], padded
    __shared__ float Bs[2][16][128];   // [buf][k][n]

    const int n0 = blockIdx.x * 128;
    const int m0 = blockIdx.y * 128;

    const float* W;
    int ldN, wn0;
    if (n0 < 256)       { W = Wh;  ldN = 256;  wn0 = n0; }
    else if (n0 < 2304) { W = Wz1; ldN = 2048; wn0 = n0 - 256; }
    else                { W = Wz2; ldN = 1024; wn0 = n0 - 2304; }

    const int tid = threadIdx.x;
    const int tx  = tid & 15;      // n
    const int ty  = tid >> 4;      // m

    // Per-thread load coordinates (fixed across k-tiles)
    const int am[2] = { (tid)          >> 2, (tid + 256) >> 2 };
    const int ak[2] = { (tid & 3) * 4,       (tid & 3) * 4 };
    const int bk[2] = { tid >> 5,            (tid + 256) >> 5 };
    const int bc[2] = { (tid & 31) * 4,      (tid & 31) * 4 };

    float acc[8][8];
    #pragma unroll
    for (int i = 0; i < 8; i++)
        #pragma unroll
        for (int j = 0; j < 8; j++) acc[i][j] = 0.f;

    float4 ra[2], rb[2];

    // prologue: tile 0
    #pragma unroll
    for (int r = 0; r < 2; r++) {
        ra[r] = *(const float4*)(X + (size_t)(m0 + am[r]) * DIN + 0 + ak[r]);
        rb[r] = *(const float4*)(W + (size_t)(0 + bk[r]) * ldN + wn0 + bc[r]);
    }
    #pragma unroll
    for (int r = 0; r < 2; r++) {
        As[0][ak[r] + 0][am[r]] = ra[r].x;
        As[0][ak[r] + 1][am[r]] = ra[r].y;
        As[0][ak[r] + 2][am[r]] = ra[r].z;
        As[0][ak[r] + 3][am[r]] = ra[r].w;
        *(float4*)(&Bs[0][bk[r]][bc[r]]) = rb[r];
    }
    __syncthreads();

    const int NT = DIN / 16;   // 32
    for (int kt = 0; kt < NT; kt++) {
        const int cur = kt & 1;
        const int nxt = cur ^ 1;
        if (kt + 1 < NT) {
            const int k0 = (kt + 1) * 16;
            #pragma unroll
            for (int r = 0; r < 2; r++) {
                ra[r] = *(const float4*)(X + (size_t)(m0 + am[r]) * DIN + k0 + ak[r]);
                rb[r] = *(const float4*)(W + (size_t)(k0 + bk[r]) * ldN + wn0 + bc[r]);
            }
        }

        #pragma unroll
        for (int kk = 0; kk < 16; kk++) {
            float a[8], b[8];
            *(float4*)(a)     = *(const float4*)(&As[cur][kk][ty * 8]);
            *(float4*)(a + 4) = *(const float4*)(&As[cur][kk][ty * 8 + 4]);
            *(float4*)(b)     = *(const float4*)(&Bs[cur][kk][tx * 8]);
            *(float4*)(b + 4) = *(const float4*)(&Bs[cur][kk][tx * 8 + 4]);
            #pragma unroll
            for (int i = 0; i < 8; i++)
                #pragma unroll
                for (int j = 0; j < 8; j++)
                    acc[i][j] = fmaf(a[i], b[j], acc[i][j]);
        }

        if (kt + 1 < NT) {
            #pragma unroll
            for (int r = 0; r < 2; r++) {
                As[nxt][ak[r] + 0][am[r]] = ra[r].x;
                As[nxt][ak[r] + 1][am[r]] = ra[r].y;
                As[nxt][ak[r] + 2][am[r]] = ra[r].z;
                As[nxt][ak[r] + 3][am[r]] = ra[r].w;
                *(float4*)(&Bs[nxt][bk[r]][bc[r]]) = rb[r];
            }
        }
        __syncthreads();
    }

    #pragma unroll
    for (int i = 0; i < 8; i++) {
        int row = m0 + ty * 8 + i;
        float* dst = g_scratch + (size_t)row * NCAT + n0 + tx * 8;
        *(float4*)(dst)     = make_float4(acc[i][0], acc[i][1], acc[i][2], acc[i][3]);
        *(float4*)(dst + 4) = make_float4(acc[i][4], acc[i][5], acc[i][6], acc[i][7]);
    }
}

// ---------------------------------------------------------------------------
// Phase 2: per-row fusion. One block (256 threads = 8 warps) per batch row.
// z1 held in registers per lane (64 floats); z2 broadcast from smem;
// tanh via MUFU.TANH.
// ---------------------------------------------------------------------------
__global__ __launch_bounds__(256, 2)
void fuse_kernel(const float* __restrict__ bh,
                 const float* __restrict__ ln_scale,
                 const float* __restrict__ ln_bias,
                 float* __restrict__ out)
{
    const int b    = blockIdx.x;
    const int tid  = threadIdx.x;
    const int lane = tid & 31;
    const int wid  = tid >> 5;

    __shared__ float z1s[NHEAD * DH];   // 2048
    __shared__ float z2s[NHEAD * DG];   // 1024
    __shared__ float hs[DH];            // 256
    __shared__ float red[2][8];

    const float* base = g_scratch + (size_t)b * NCAT;

    // load z1, z2 into shared (vectorized)
    #pragma unroll
    for (int r = 0; r < 2; r++) {
        int f = tid + r * 256;
        ((float4*)z1s)[f] = ((const float4*)(base + 256))[f];
    }
    ((float4*)z2s)[tid] = ((const float4*)(base + 2304))[tid];

    // relu + bias + LayerNorm on the 256-wide branch
    float v = fmaxf(base[tid] + bh[tid], 0.f);
    float s = v, q = v * v;
    #pragma unroll
    for (int o = 16; o; o >>= 1) {
        s += __shfl_xor_sync(0xffffffffu, s, o);
        q += __shfl_xor_sync(0xffffffffu, q, o);
    }
    if (lane == 0) { red[0][wid] = s; red[1][wid] = q; }
    __syncthreads();
    float ts = 0.f, tq = 0.f;
    #pragma unroll
    for (int i = 0; i < 8; i++) { ts += red[0][i]; tq += red[1][i]; }
    const float mu_ln  = ts * (1.f / 256.f);
    const float var_ln = tq * (1.f / 256.f) - mu_ln * mu_ln;
    const float inv_ln = rsqrtf(var_ln + 1e-6f);
    const float hv = (v - mu_ln) * inv_ln * ln_scale[tid] + ln_bias[tid];
    hs[tid] = hv;
    out[(size_t)b * DH + tid] = hv;
    __syncthreads();

    // z1 + h into registers (per lane: d = j*32+lane, j=0..7)
    float z1r[NHEAD][8];
    #pragma unroll
    for (int h = 0; h < NHEAD; h++)
        #pragma unroll
        for (int j = 0; j < 8; j++)
            z1r[h][j] = z1s[h * DH + j * 32 + lane];
    float hr[8];
    #pragma unroll
    for (int j = 0; j < 8; j++) hr[j] = hs[j * 32 + lane];

    float* out_y = out + (size_t)BROWS * DH;
    #pragma unroll 1
    for (int gi = 0; gi < 16; gi++) {
        const int g = wid * 16 + gi;

        float zc[NHEAD];
        #pragma unroll
        for (int h = 0; h < NHEAD; h++) zc[h] = z2s[h * DG + g];  // broadcast

        float wv[8];
        float sw = 0.f, qw = 0.f;
        #pragma unroll
        for (int j = 0; j < 8; j++) {
            float a = 0.f;
            #pragma unroll
            for (int h = 0; h < NHEAD; h++)
                a = fmaf(zc[h], z1r[h][j], a);
            wv[j] = a;
            sw += a;
            qw = fmaf(a, a, qw);
        }
        #pragma unroll
        for (int o = 16; o; o >>= 1) {
            sw += __shfl_xor_sync(0xffffffffu, sw, o);
            qw += __shfl_xor_sync(0xffffffffu, qw, o);
        }
        const float mu  = sw * (1.f / 256.f);
        const float var = fmaxf(qw * (1.f / 256.f) - mu * mu, 0.f);
        const float sd  = sqrtf(var);
        const float inv = 1.f / (sd + 1e-6f);

        float y = 0.f;
        #pragma unroll
        for (int j = 0; j < 8; j++)
            y = fmaf(tanh_fast((wv[j] - mu) * inv), hr[j], y);
        #pragma unroll
        for (int o = 16; o; o >>= 1)
            y += __shfl_xor_sync(0xffffffffu, y, o);
        if (lane == 0) out_y[(size_t)b * DG + g] = y;
    }
}

// ---------------------------------------------------------------------------
extern "C" void kernel_launch(void* const* d_in, const int* in_sizes, int n_in,
                              void* d_out, int out_size)
{
    const float* x        = (const float*)d_in[0];
    const float* Wh       = (const float*)d_in[1];
    const float* bh       = (const float*)d_in[2];
    const float* Wz1      = (const float*)d_in[3];
    const float* Wz2      = (const float*)d_in[4];
    const float* ln_scale = (const float*)d_in[5];
    const float* ln_bias  = (const float*)d_in[6];
    float* out = (float*)d_out;

    dim3 g1(NCAT / 128, BROWS / 128);   // 26 x 32
    gemm_cat_kernel<<<g1, 256>>>(x, Wh, Wz1, Wz2);
    fuse_kernel<<<BROWS, 256>>>(bh, ln_scale, ln_bias, out);
}